// round 10
// baseline (speedup 1.0000x reference)
#include <cuda_runtime.h>
#include <math.h>

// Problem dims
#define BATCH 512
#define TT    512
#define DD    128   // input / decoder hidden
#define HH    64    // encoder hidden

#define GE 256      // encoder gates 4H
#define GD 512      // decoder gates 4D
#define KD 128      // decoder K = D

typedef unsigned long long u64t;

// ---------------- device scratch (static: no allocation) ----------------
__device__ __align__(16) float g_WencR[HH * GE];       // encoder Whh, k-paired: (k,j) -> (k>>1)*512 + j*2 + (k&1)
__device__ __align__(16) float g_WencP[DD * GE];       // encoder Wih^T [k][j], tf32-rounded (phase-A B operand)
__device__ __align__(16) float g_Wdec_t[KD * 384];     // decoder i,f,g k-paired
__device__ __align__(16) float g_Wo4  [KD * 128];      // decoder o-gate k-quad
__device__ __align__(16) float g_Wihd_t[HH * GD];      // decoder input proj [k][j]
__device__ __align__(16) float g_henc  [BATCH * HH];   // encoder final hidden
__device__ float g_XP[(size_t)BATCH * TT * GE];        // 256MB: encoder input projection [b*T+t][j]

// ---------------- helpers ----------------
__device__ __forceinline__ u64t d2(float a) {
    u64t r; asm("mov.b64 %0, {%1, %1};" : "=l"(r) : "f"(a)); return r;
}
__device__ __forceinline__ u64t pk2(float x, float y) {
    u64t r; asm("mov.b64 %0, {%1, %2};" : "=l"(r) : "f"(x), "f"(y)); return r;
}
__device__ __forceinline__ u64t fma2(u64t a, u64t b, u64t c) {
    asm("fma.rn.f32x2 %0, %1, %2, %3;" : "=l"(c) : "l"(a), "l"(b), "l"(c));
    return c;
}
__device__ __forceinline__ float2 unpk(u64t v) {
    float2 r; asm("mov.b64 {%0, %1}, %2;" : "=f"(r.x), "=f"(r.y) : "l"(v)); return r;
}
__device__ __forceinline__ void lds_v2u64(u64t& x, u64t& y, unsigned addr) {
    asm volatile("ld.shared.v2.u64 {%0, %1}, [%2];" : "=l"(x), "=l"(y) : "r"(addr));
}
__device__ __forceinline__ float2 lds_f2(unsigned addr) {
    float2 v; asm volatile("ld.shared.v2.f32 {%0, %1}, [%2];" : "=f"(v.x), "=f"(v.y) : "r"(addr));
    return v;
}
__device__ __forceinline__ float tanh_ap(float x) {
    asm("tanh.approx.f32 %0, %0;" : "+f"(x)); return x;
}
__device__ __forceinline__ float sig_ap(float x) {
    return fmaf(tanh_ap(0.5f * x), 0.5f, 0.5f);
}
__device__ __forceinline__ unsigned tf32r(float f) {
    unsigned u; asm("cvt.rna.tf32.f32 %0, %1;" : "=r"(u) : "f"(f)); return u;
}
__device__ __forceinline__ void mma_tf32(float d[4],
                                         unsigned a0, unsigned a1, unsigned a2, unsigned a3,
                                         unsigned b0, unsigned b1) {
    asm volatile(
        "mma.sync.aligned.m16n8k8.row.col.f32.tf32.tf32.f32 "
        "{%0,%1,%2,%3}, {%4,%5,%6,%7}, {%8,%9}, {%0,%1,%2,%3};"
        : "+f"(d[0]), "+f"(d[1]), "+f"(d[2]), "+f"(d[3])
        : "r"(a0), "r"(a1), "r"(a2), "r"(a3), "r"(b0), "r"(b1));
}

// ---------------- prep: transpose + re-tile all weights (one-time, tiny) ----------------
__global__ void prep_kernel(const float* __restrict__ Wih_e,
                            const float* __restrict__ Whh_e,
                            const float* __restrict__ Whh_d,
                            const float* __restrict__ Wih_d) {
    int idx = blockIdx.x * 256 + threadIdx.x;            // 0 .. 147455
    if (idx < HH * GE) {                                 // 16384: encoder Whh, k-paired
        int r = idx & 1, j = (idx >> 1) & 255, p = idx >> 9;
        int k = 2 * p + r;
        g_WencR[idx] = Whh_e[j * HH + k];
        return;
    }
    int i1 = idx - HH * GE;
    if (i1 < DD * GE) {                                  // 32768: encoder Wih^T, tf32-rounded
        int k = i1 >> 8, j = i1 & 255;
        g_WencP[i1] = __uint_as_float(tf32r(Wih_e[j * DD + k]));
        return;
    }
    int i2 = i1 - DD * GE;
    if (i2 < KD * 384) {                                 // 49152: decoder i,f,g, k-paired
        int r = i2 & 1, j = (i2 >> 1) % 384, k2 = i2 / 768;
        int k = 2 * k2 + r;
        g_Wdec_t[i2] = Whh_d[j * 128 + k];
        return;
    }
    int i3 = i2 - KD * 384;
    if (i3 < KD * 128) {                                 // 16384: decoder o-gate, k-quad
        int r = i3 & 3, jo = (i3 >> 2) & 127, k4 = i3 >> 9;
        int k = 4 * k4 + r;
        g_Wo4[i3] = Whh_d[(384 + jo) * 128 + k];
        return;
    }
    int i4 = i3 - KD * 128;
    if (i4 < HH * GD) {                                  // 32768: decoder input proj [k][j]
        int k = i4 >> 9, j = i4 & 511;
        g_Wihd_t[i4] = Wih_d[j * 64 + k];
    }
}

// ---------------- phase A: XP[r][j] = x_row(r) . Wih_e[j] + b_e[j], tf32 mma.sync ----------------
// grid (4096, 2), 256 threads, 2 CTAs/SM. CTA tile: M=64 rows, N=128 gates, K=128.
// SMEM: xs[64][132] f32 | ws[128][136] f32 | bs[128]
#define PA_XS_STRIDE 132
#define PA_WS_STRIDE 136
#define PA_WS_F  (64 * PA_XS_STRIDE)
#define PA_BS_F  (PA_WS_F + 128 * PA_WS_STRIDE)
#define PA_SMEM_F (PA_BS_F + 128)
#define PA_SMEM_BYTES (PA_SMEM_F * 4)

__global__ __launch_bounds__(256, 2)
void phaseA_kernel(const float* __restrict__ x, const float* __restrict__ b_e) {
    extern __shared__ float sm[];
    float* xs = sm;
    float* ws = sm + PA_WS_F;
    float* bs = sm + PA_BS_F;

    const int tid = threadIdx.x;
    const int Mbase = blockIdx.x * 64;
    const int jbase = blockIdx.y * 128;

    // load + tf32-round x tile [64 x 128]
    #pragma unroll
    for (int i = 0; i < 8; ++i) {
        int f4 = tid + i * 256;                 // 2048 float4s
        int row = f4 >> 5, c4 = (f4 & 31) * 4;
        float4 v = *(const float4*)&x[(size_t)(Mbase + row) * DD + c4];
        float* d = &xs[row * PA_XS_STRIDE + c4];
        d[0] = __uint_as_float(tf32r(v.x));
        d[1] = __uint_as_float(tf32r(v.y));
        d[2] = __uint_as_float(tf32r(v.z));
        d[3] = __uint_as_float(tf32r(v.w));
    }
    // load W tile [128 k x 128 n] (pre-rounded)
    #pragma unroll
    for (int i = 0; i < 16; ++i) {
        int f4 = tid + i * 256;                 // 4096 float4s
        int row = f4 >> 5, c4 = (f4 & 31) * 4;
        float4 v = *(const float4*)&g_WencP[row * GE + jbase + c4];
        *(float4*)&ws[row * PA_WS_STRIDE + c4] = v;
    }
    if (tid < 128) bs[tid] = b_e[jbase + tid];
    __syncthreads();

    const int l = tid & 31, wid = tid >> 5;
    const int wm = wid & 3, wn = wid >> 2;      // 4 M-tiles x 2 N-halves
    const int gr = l >> 2, gc = l & 3;

    float d[8][4];
    #pragma unroll
    for (int nt = 0; nt < 8; ++nt)
        d[nt][0] = d[nt][1] = d[nt][2] = d[nt][3] = 0.0f;

    const float* xsw = xs + (wm * 16) * PA_XS_STRIDE;
    #pragma unroll
    for (int k8 = 0; k8 < 16; ++k8) {
        const int kb = k8 * 8;
        unsigned a0 = __float_as_uint(xsw[gr * PA_XS_STRIDE + kb + gc]);
        unsigned a1 = __float_as_uint(xsw[(gr + 8) * PA_XS_STRIDE + kb + gc]);
        unsigned a2 = __float_as_uint(xsw[gr * PA_XS_STRIDE + kb + gc + 4]);
        unsigned a3 = __float_as_uint(xsw[(gr + 8) * PA_XS_STRIDE + kb + gc + 4]);
        #pragma unroll
        for (int nt = 0; nt < 8; ++nt) {
            int nc = wn * 64 + nt * 8 + gr;
            unsigned b0 = __float_as_uint(ws[(kb + gc) * PA_WS_STRIDE + nc]);
            unsigned b1 = __float_as_uint(ws[(kb + gc + 4) * PA_WS_STRIDE + nc]);
            mma_tf32(d[nt], a0, a1, a2, a3, b0, b1);
        }
    }

    const int row0 = Mbase + wm * 16 + gr;
    #pragma unroll
    for (int nt = 0; nt < 8; ++nt) {
        int cj = wn * 64 + nt * 8 + gc * 2;     // col within CTA N-tile
        float bA = bs[cj], bB = bs[cj + 1];
        size_t col = (size_t)(jbase + cj);
        *(float2*)&g_XP[(size_t)row0 * GE + col] =
            make_float2(d[nt][0] + bA, d[nt][1] + bB);
        *(float2*)&g_XP[(size_t)(row0 + 8) * GE + col] =
            make_float2(d[nt][2] + bA, d[nt][3] + bB);
    }
}

// ---------------- encoder: recurrence only (K=64), scalar f32x2 ----------------
// 128 CTAs x 4 batch rows, 256 threads.
// SMEM: Wt 65536B | hbuf[64][4] 1024B | gbuf[4][256] 4096B
#define ENC_SMEM_F (HH * GE + HH * 4 + 4 * GE)
#define ENC_SMEM_BYTES (ENC_SMEM_F * 4)

__global__ __launch_bounds__(256, 1)
void enc_kernel(void) {
    extern __shared__ float sm[];
    float* Wt   = sm;                       // 16384 floats (k-paired)
    float* hbuf = sm + HH * GE;             // 256  [k][b]
    float* gbuf = hbuf + HH * 4;            // 1024 [b][j]

    const int tid = threadIdx.x;
    const int bb  = blockIdx.x * 4;

    {
        const float4* src = (const float4*)g_WencR;
        float4* dst = (float4*)Wt;
        #pragma unroll 4
        for (int i = tid; i < (HH * GE) / 4; i += 256) dst[i] = src[i];
    }
    hbuf[tid] = 0.0f;                       // 256 floats = whole hbuf

    const int eb = tid >> 6, ej = tid & 63;
    const unsigned Wb = (unsigned)__cvta_generic_to_shared(Wt) + tid * 8;
    const unsigned Ib = (unsigned)__cvta_generic_to_shared(hbuf);

    // xp for t=0 (4 batches, this thread's gate j = tid)
    float4 xpre;
    xpre.x = g_XP[((size_t)(bb + 0) * TT + 0) * GE + tid];
    xpre.y = g_XP[((size_t)(bb + 1) * TT + 0) * GE + tid];
    xpre.z = g_XP[((size_t)(bb + 2) * TT + 0) * GE + tid];
    xpre.w = g_XP[((size_t)(bb + 3) * TT + 0) * GE + tid];

    float creg = 0.0f;
    float hlast = 0.0f;
    __syncthreads();

    for (int t = 0; t < TT; ++t) {
        u64t a01 = pk2(xpre.x, xpre.y), a23 = pk2(xpre.z, xpre.w);

        // prefetch xp_{t+1} (overlaps the K-loop below)
        float4 xnext = xpre;
        if (t + 1 < TT) {
            xnext.x = g_XP[((size_t)(bb + 0) * TT + (t + 1)) * GE + tid];
            xnext.y = g_XP[((size_t)(bb + 1) * TT + (t + 1)) * GE + tid];
            xnext.z = g_XP[((size_t)(bb + 2) * TT + (t + 1)) * GE + tid];
            xnext.w = g_XP[((size_t)(bb + 3) * TT + (t + 1)) * GE + tid];
        }

        unsigned wa = Wb, ia = Ib;
        #pragma unroll 8
        for (int k2 = 0; k2 < 32; ++k2) {
            float2 w = lds_f2(wa);
            u64t i0a, i0b, i1a, i1b;
            lds_v2u64(i0a, i0b, ia);
            lds_v2u64(i1a, i1b, ia + 16);
            u64t w0 = d2(w.x), w1 = d2(w.y);
            a01 = fma2(w0, i0a, a01); a23 = fma2(w0, i0b, a23);
            a01 = fma2(w1, i1a, a01); a23 = fma2(w1, i1b, a23);
            wa += GE * 8;   // 2048
            ia += 32;
        }
        float2 v01 = unpk(a01), v23 = unpk(a23);
        gbuf[tid] = v01.x; gbuf[256 + tid] = v01.y;
        gbuf[512 + tid] = v23.x; gbuf[768 + tid] = v23.y;
        __syncthreads();

        float gi = gbuf[eb * 256 + ej];
        float gf = gbuf[eb * 256 + 64 + ej];
        float gg = gbuf[eb * 256 + 128 + ej];
        float go = gbuf[eb * 256 + 192 + ej];
        float i_ = sig_ap(gi), f_ = sig_ap(gf), g_ = tanh_ap(gg), o_ = sig_ap(go);
        creg = f_ * creg + i_ * g_;
        hlast = o_ * tanh_ap(creg);
        hbuf[ej * 4 + eb] = hlast;
        xpre = xnext;
        __syncthreads();
    }
    g_henc[(bb + eb) * HH + ej] = hlast;
}

// ---------------- decoder: unchanged scalar f32x2 path (R7, passing) ----------------
#define DEC_SMEM_FLOATS (KD*384 + 4*GD + 4*GD + KD*4)
#define DEC_SMEM_BYTES  (DEC_SMEM_FLOATS * 4)

__global__ __launch_bounds__(512, 1)
void dec_kernel(const float* __restrict__ b_d, float* __restrict__ out) {
    extern __shared__ float sm[];
    float* Wd   = sm;                 // 49152 (k-paired)
    float* xp   = sm + KD * 384;      // 2048 [j][b]
    float* gbuf = xp + 4 * GD;        // 2048 [b][j]
    float* hsm  = gbuf + 4 * GD;      // 512  [k][b]

    const int tid = threadIdx.x;
    const int bb  = blockIdx.x * 4;

    {
        const float4* src = (const float4*)g_Wdec_t;
        float4* dst = (float4*)Wd;
        #pragma unroll 4
        for (int i = tid; i < (KD * 384) / 4; i += 512) dst[i] = src[i];
    }
    if (tid < 256) gbuf[tid] = g_henc[(bb + (tid >> 6)) * HH + (tid & 63)];
    hsm[tid] = 0.0f;
    __syncthreads();

    {
        const int j = tid;
        float a0 = b_d[j], a1 = a0, a2 = a0, a3 = a0;
        #pragma unroll 4
        for (int k = 0; k < HH; ++k) {
            float w = g_Wihd_t[k * GD + j];
            a0 = fmaf(w, gbuf[k], a0);
            a1 = fmaf(w, gbuf[64 + k], a1);
            a2 = fmaf(w, gbuf[128 + k], a2);
            a3 = fmaf(w, gbuf[192 + k], a3);
        }
        float4* xpv = (float4*)&xp[j * 4];
        *xpv = make_float4(a0, a1, a2, a3);
    }
    __syncthreads();

    float c_reg = 0.0f;
    const int eb = tid >> 7, ej = tid & 127;
    const unsigned Hb = (unsigned)__cvta_generic_to_shared(hsm);
    const unsigned Xb = (unsigned)__cvta_generic_to_shared(xp) + tid * 16;
    const unsigned Wb = (unsigned)__cvta_generic_to_shared(Wd) + tid * 8;
    const int jo = tid - 384;
    const float4* Wo = (const float4*)g_Wo4 + (jo >= 0 ? jo : 0);

    for (int t = 0; t < TT; ++t) {
        u64t a01, a23;
        lds_v2u64(a01, a23, Xb);

        if (tid < 384) {
            unsigned wa = Wb, ha = Hb;
            #pragma unroll 8
            for (int k2 = 0; k2 < 64; ++k2) {
                float2 w = lds_f2(wa);
                u64t h0a, h0b, h1a, h1b;
                lds_v2u64(h0a, h0b, ha);
                lds_v2u64(h1a, h1b, ha + 16);
                u64t w0 = d2(w.x), w1 = d2(w.y);
                a01 = fma2(w0, h0a, a01); a23 = fma2(w0, h0b, a23);
                a01 = fma2(w1, h1a, a01); a23 = fma2(w1, h1b, a23);
                wa += 384 * 8;
                ha += 32;
            }
        } else {
            unsigned ha = Hb;
            #pragma unroll 8
            for (int k4 = 0; k4 < 32; ++k4) {
                float4 w = __ldg(&Wo[k4 * 128]);
                u64t pa, pb;
                lds_v2u64(pa, pb, ha);
                a01 = fma2(d2(w.x), pa, a01); a23 = fma2(d2(w.x), pb, a23);
                lds_v2u64(pa, pb, ha + 16);
                a01 = fma2(d2(w.y), pa, a01); a23 = fma2(d2(w.y), pb, a23);
                lds_v2u64(pa, pb, ha + 32);
                a01 = fma2(d2(w.z), pa, a01); a23 = fma2(d2(w.z), pb, a23);
                lds_v2u64(pa, pb, ha + 48);
                a01 = fma2(d2(w.w), pa, a01); a23 = fma2(d2(w.w), pb, a23);
                ha += 64;
            }
        }
        float2 v01 = unpk(a01), v23 = unpk(a23);
        gbuf[tid] = v01.x; gbuf[512 + tid] = v01.y;
        gbuf[1024 + tid] = v23.x; gbuf[1536 + tid] = v23.y;
        __syncthreads();

        float gi = gbuf[eb * 512 + ej];
        float gf = gbuf[eb * 512 + 128 + ej];
        float gg = gbuf[eb * 512 + 256 + ej];
        float go = gbuf[eb * 512 + 384 + ej];
        float i_ = sig_ap(gi), f_ = sig_ap(gf), g_ = tanh_ap(gg), o_ = sig_ap(go);
        c_reg = f_ * c_reg + i_ * g_;
        float h_ = o_ * tanh_ap(c_reg);
        hsm[ej * 4 + eb] = h_;
        out[((size_t)(bb + eb) * TT + t) * DD + ej] = h_;
        __syncthreads();
    }
}

// ---------------- launch ----------------
extern "C" void kernel_launch(void* const* d_in, const int* in_sizes, int n_in,
                              void* d_out, int out_size) {
    const float* x     = (const float*)d_in[0];
    const float* Wih_e = (const float*)d_in[1];
    const float* Whh_e = (const float*)d_in[2];
    const float* b_e   = (const float*)d_in[3];
    const float* Wih_d = (const float*)d_in[4];
    const float* Whh_d = (const float*)d_in[5];
    const float* b_d   = (const float*)d_in[6];
    float* out = (float*)d_out;

    cudaFuncSetAttribute(phaseA_kernel, cudaFuncAttributeMaxDynamicSharedMemorySize, PA_SMEM_BYTES);
    cudaFuncSetAttribute(enc_kernel, cudaFuncAttributeMaxDynamicSharedMemorySize, ENC_SMEM_BYTES);
    cudaFuncSetAttribute(dec_kernel, cudaFuncAttributeMaxDynamicSharedMemorySize, DEC_SMEM_BYTES);

    prep_kernel<<<576, 256>>>(Wih_e, Whh_e, Whh_d, Wih_d);
    dim3 gA((BATCH * TT) / 64, 2);
    phaseA_kernel<<<gA, 256, PA_SMEM_BYTES>>>(x, b_e);
    enc_kernel<<<BATCH / 4, 256, ENC_SMEM_BYTES>>>();
    dec_kernel<<<BATCH / 4, 512, DEC_SMEM_BYTES>>>(b_d, out);
}

// round 11
// speedup vs baseline: 1.9212x; 1.9212x over previous
#include <cuda_runtime.h>
#include <math.h>

// Problem dims
#define BATCH 512
#define TT    512
#define DD    128
#define HH    64

#define GE 256      // encoder gates 4H
#define KE 192      // encoder K = D + H
#define GD 512      // decoder gates 4D
#define KD 128      // decoder K = D

typedef unsigned long long u64t;

// ---------------- device scratch ----------------
__device__ __align__(16) float g_Wenc_t[KE * GE];      // encoder concat, k-paired (R7 layout)
__device__ __align__(16) float g_WdFrag[2 * 16 * 16 * 128]; // 65536: decoder Whh tf32 mma fragments
__device__ __align__(16) float g_Wihd2[2 * HH * 256];  // 32768: decoder input proj [role][k][local row]
__device__ __align__(16) float g_henc  [BATCH * HH];

// ---------------- helpers ----------------
__device__ __forceinline__ u64t d2(float a) {
    u64t r; asm("mov.b64 %0, {%1, %1};" : "=l"(r) : "f"(a)); return r;
}
__device__ __forceinline__ u64t fma2(u64t a, u64t b, u64t c) {
    asm("fma.rn.f32x2 %0, %1, %2, %3;" : "=l"(c) : "l"(a), "l"(b), "l"(c));
    return c;
}
__device__ __forceinline__ float2 unpk(u64t v) {
    float2 r; asm("mov.b64 {%0, %1}, %2;" : "=f"(r.x), "=f"(r.y) : "l"(v)); return r;
}
__device__ __forceinline__ void lds_v2u64(u64t& x, u64t& y, unsigned addr) {
    asm volatile("ld.shared.v2.u64 {%0, %1}, [%2];" : "=l"(x), "=l"(y) : "r"(addr));
}
__device__ __forceinline__ float2 lds_f2(unsigned addr) {
    float2 v; asm volatile("ld.shared.v2.f32 {%0, %1}, [%2];" : "=f"(v.x), "=f"(v.y) : "r"(addr));
    return v;
}
__device__ __forceinline__ float tanh_ap(float x) {
    asm("tanh.approx.f32 %0, %0;" : "+f"(x)); return x;
}
__device__ __forceinline__ float sig_ap(float x) {
    return fmaf(tanh_ap(0.5f * x), 0.5f, 0.5f);
}
__device__ __forceinline__ unsigned tf32r(float f) {
    unsigned u; asm("cvt.rna.tf32.f32 %0, %1;" : "=r"(u) : "f"(f)); return u;
}
__device__ __forceinline__ void mma_tf32(float d[4],
                                         unsigned a0, unsigned a1, unsigned a2, unsigned a3,
                                         unsigned b0, unsigned b1) {
    asm volatile(
        "mma.sync.aligned.m16n8k8.row.col.f32.tf32.tf32.f32 "
        "{%0,%1,%2,%3}, {%4,%5,%6,%7}, {%8,%9}, {%0,%1,%2,%3};"
        : "+f"(d[0]), "+f"(d[1]), "+f"(d[2]), "+f"(d[3])
        : "r"(a0), "r"(a1), "r"(a2), "r"(a3), "r"(b0), "r"(b1));
}
#define CLUSTER_SYNC() do { \
    asm volatile("barrier.cluster.arrive.aligned;" ::: "memory"); \
    asm volatile("barrier.cluster.wait.aligned;" ::: "memory"); \
} while (0)

// ---------------- prep ----------------
__global__ void prep_kernel(const float* __restrict__ Wih_e,
                            const float* __restrict__ Whh_e,
                            const float* __restrict__ Whh_d,
                            const float* __restrict__ Wih_d) {
    int idx = blockIdx.x * 256 + threadIdx.x;            // 0 .. 147455
    if (idx < KE * GE) {                                 // 49152: encoder concat, k-paired
        int r = idx & 1, j = (idx >> 1) & 255, k2 = idx >> 9;
        int k = 2 * k2 + r;
        g_Wenc_t[idx] = (k < 128) ? Wih_e[j * 128 + k] : Whh_e[j * 64 + (k - 128)];
        return;
    }
    int f = idx - KE * GE;
    if (f < 65536) {                                     // decoder Whh mma fragments, tf32
        int rw = f >> 11;                                // (role, warp) block of 2048 floats
        int role = rw >> 4, w = rw & 15;
        int rem = f & 2047;
        int i4 = rem >> 7;                               // k-tile
        int r2 = rem & 127;
        int l = r2 >> 2, c = r2 & 3;                     // lane, fragment slot a0..a3
        int gr = l >> 2, gc = l & 3;
        int lrow = w * 16 + gr + (c & 1) * 8;            // local row 0..255
        int k = i4 * 8 + gc + ((c >> 1) & 1) * 4;
        int gate = lrow >> 6, j = lrow & 63;
        int grow = gate * 128 + role * 64 + j;           // global gate row
        g_WdFrag[f] = __uint_as_float(tf32r(Whh_d[grow * 128 + k]));
        return;
    }
    int f2 = f - 65536;
    if (f2 < 32768) {                                    // decoder input proj [role][k][lrow]
        int rolek = f2 >> 8, lr = f2 & 255;
        int role = rolek >> 6, k = rolek & 63;
        int gate = lr >> 6, j = lr & 63;
        int grow = gate * 128 + role * 64 + j;
        g_Wihd2[f2] = Wih_d[grow * 64 + k];
    }
}

// ---------------- encoder: R7 fused kernel (fp32, f32x2) — proven ----------------
#define ENC_SMEM_FLOATS (KE*GE + KE*4 + 4*GE + GE)
#define ENC_SMEM_BYTES  (ENC_SMEM_FLOATS * 4)

__global__ __launch_bounds__(256, 1)
void enc_kernel(const float* __restrict__ x, const float* __restrict__ b_e) {
    extern __shared__ float sm[];
    float* Wt   = sm;                       // 49152 (k-paired)
    float* inp  = sm + KE * GE;             // 768  [k][b]
    float* gbuf = inp + KE * 4;             // 1024 [b][j]
    float* bias = gbuf + 4 * GE;            // 256

    const int tid = threadIdx.x;
    const int bb  = blockIdx.x * 4;

    {
        const float4* src = (const float4*)g_Wenc_t;
        float4* dst = (float4*)Wt;
        #pragma unroll 4
        for (int i = tid; i < (KE * GE) / 4; i += 256) dst[i] = src[i];
    }
    bias[tid] = b_e[tid];
    {
        int b = tid >> 6, kk = (tid & 63) * 2;
        float2 v = *(const float2*)&x[(size_t)(bb + b) * TT * DD + kk];
        inp[kk * 4 + b]       = v.x;
        inp[(kk + 1) * 4 + b] = v.y;
        inp[(128 + (tid >> 2)) * 4 + (tid & 3)] = 0.0f;
    }
    float c_reg = 0.0f;
    const int eb = tid >> 6, ej = tid & 63;
    const unsigned Wb = (unsigned)__cvta_generic_to_shared(Wt) + tid * 8;
    const unsigned Ib = (unsigned)__cvta_generic_to_shared(inp);
    __syncthreads();

    for (int t = 0; t < TT; ++t) {
        float2 xpre = make_float2(0.0f, 0.0f);
        const int pb = tid >> 6, pk = (tid & 63) * 2;
        if (t + 1 < TT)
            xpre = *(const float2*)&x[(size_t)(bb + pb) * TT * DD + (size_t)(t + 1) * DD + pk];

        float bj = bias[tid];
        u64t a01 = d2(bj), a23 = d2(bj);
        unsigned wa = Wb, ia = Ib;
        #pragma unroll 8
        for (int k2 = 0; k2 < 96; ++k2) {
            float2 w = lds_f2(wa);
            u64t i0a, i0b, i1a, i1b;
            lds_v2u64(i0a, i0b, ia);
            lds_v2u64(i1a, i1b, ia + 16);
            u64t w0 = d2(w.x), w1 = d2(w.y);
            a01 = fma2(w0, i0a, a01); a23 = fma2(w0, i0b, a23);
            a01 = fma2(w1, i1a, a01); a23 = fma2(w1, i1b, a23);
            wa += GE * 8;
            ia += 32;
        }
        float2 v01 = unpk(a01), v23 = unpk(a23);
        gbuf[tid] = v01.x; gbuf[256 + tid] = v01.y;
        gbuf[512 + tid] = v23.x; gbuf[768 + tid] = v23.y;
        __syncthreads();

        float gi = gbuf[eb * 256 + ej];
        float gf = gbuf[eb * 256 + 64 + ej];
        float gg = gbuf[eb * 256 + 128 + ej];
        float go = gbuf[eb * 256 + 192 + ej];
        float i_ = sig_ap(gi), f_ = sig_ap(gf), g_ = tanh_ap(gg), o_ = sig_ap(go);
        c_reg = f_ * c_reg + i_ * g_;
        float h_ = o_ * tanh_ap(c_reg);
        inp[(128 + ej) * 4 + eb] = h_;
        inp[pk * 4 + pb]       = xpre.x;
        inp[(pk + 1) * 4 + pb] = xpre.y;
        __syncthreads();

        if (t == TT - 1) g_henc[(bb + eb) * HH + ej] = h_;
    }
}

// ---------------- decoder: 2-CTA cluster, register-resident tf32 mma recurrence ----------------
// 64 clusters x 2 CTAs x 8 batches; 512 threads/CTA; each CTA owns 256 gate rows
// (its 64 h-dims' i,f,g,o), weights live in registers as mma fragments.
// SMEM floats: hsm[2][128][8] 2048 | xp[256][8] 2048 | gsm[256][10] 2560
#define DEC_SMEM_F (2048 + 2048 + 2560)
#define DEC_SMEM_BYTES (DEC_SMEM_F * 4)

__global__ __launch_bounds__(512, 1) __cluster_dims__(2, 1, 1)
void dec_kernel(const float* __restrict__ b_d, float* __restrict__ out) {
    extern __shared__ float sm[];
    float* hsm = sm;              // [2][128 k][8 b]  double-buffered hidden
    float* xp  = sm + 2048;       // [256 lrow][8 b]  constant gate bias
    float* gsm = sm + 4096;       // [256 lrow][10]   per-step gates
    float* hesm = gsm;            // reuse: [8 b][64 k] h_enc staging

    const int tid = threadIdx.x;
    const int w = tid >> 5, l = tid & 31;
    unsigned rank;
    asm("mov.u32 %0, %%cluster_ctarank;" : "=r"(rank));
    const int bb   = (blockIdx.x >> 1) * 8;
    const int koff = (int)rank * 64;

    // A fragments: 16 k-tiles x float4 (a0..a3), coalesced
    float4 af[16];
    {
        const float4* Asrc = (const float4*)g_WdFrag + ((int)rank * 16 + w) * 512;
        #pragma unroll
        for (int i4 = 0; i4 < 16; ++i4) af[i4] = Asrc[i4 * 32 + l];
    }

    // zero both h buffers; stage h_enc
    hsm[tid] = 0.0f; hsm[512 + tid] = 0.0f;
    hsm[1024 + tid] = 0.0f; hsm[1536 + tid] = 0.0f;
    hesm[tid] = g_henc[bb * 64 + tid];            // [b][k], b=tid>>6, k=tid&63
    __syncthreads();

    // one-time input projection: xp[lrow][b] = b_d[grow] + sum_k Wih_d[grow][k] h_enc[b][k]
    {
        int lr = tid >> 1, b4 = (tid & 1) * 4;
        int gate = lr >> 6, j = lr & 63;
        int grow = gate * 128 + koff + j;
        float a0 = b_d[grow], a1 = a0, a2 = a0, a3 = a0;
        #pragma unroll 4
        for (int k = 0; k < HH; ++k) {
            float ww = g_Wihd2[((int)rank * 64 + k) * 256 + lr];
            a0 = fmaf(ww, hesm[(b4 + 0) * 64 + k], a0);
            a1 = fmaf(ww, hesm[(b4 + 1) * 64 + k], a1);
            a2 = fmaf(ww, hesm[(b4 + 2) * 64 + k], a2);
            a3 = fmaf(ww, hesm[(b4 + 3) * 64 + k], a3);
        }
        *(float4*)&xp[lr * 8 + b4] = make_float4(a0, a1, a2, a3);
    }
    __syncthreads();
    CLUSTER_SYNC();

    const int gr = l >> 2, gc = l & 3;
    const int wbase = w * 16;
    const int ej = tid & 63, ebb = tid >> 6;      // elementwise identity (h-dim, batch)
    float creg = 0.0f;

    // DSMEM remote base for peer's hsm
    unsigned hU = (unsigned)__cvta_generic_to_shared(hsm);
    unsigned remBase;
    asm("mapa.shared::cluster.u32 %0, %1, %2;" : "=r"(remBase) : "r"(hU), "r"(rank ^ 1u));
    const unsigned myoff = (unsigned)(((koff + ej) * 8 + ebb) * 4);

    for (int t = 0; t < TT; ++t) {
        const float* hr = hsm + (((t & 1) ^ 1) << 10);   // read buffer
        const int wb = (t & 1) << 10;                    // write buffer (float offset)

        // acc init from xp (fp32 bias path — exact)
        float2 x01 = *(const float2*)&xp[(wbase + gr) * 8 + 2 * gc];
        float2 x23 = *(const float2*)&xp[(wbase + gr + 8) * 8 + 2 * gc];
        float dd[4] = {x01.x, x01.y, x23.x, x23.y};

        #pragma unroll
        for (int kt = 0; kt < 16; ++kt) {
            float b0 = hr[(kt * 8 + gc) * 8 + gr];
            float b1 = hr[(kt * 8 + gc + 4) * 8 + gr];
            mma_tf32(dd,
                     __float_as_uint(af[kt].x), __float_as_uint(af[kt].y),
                     __float_as_uint(af[kt].z), __float_as_uint(af[kt].w),
                     __float_as_uint(b0), __float_as_uint(b1));
        }
        *(float2*)&gsm[(wbase + gr) * 10 + 2 * gc]     = make_float2(dd[0], dd[1]);
        *(float2*)&gsm[(wbase + gr + 8) * 10 + 2 * gc] = make_float2(dd[2], dd[3]);
        __syncthreads();

        float gi = gsm[(ej)       * 10 + ebb];
        float gf = gsm[(64 + ej)  * 10 + ebb];
        float gg = gsm[(128 + ej) * 10 + ebb];
        float go = gsm[(192 + ej) * 10 + ebb];
        float i_ = sig_ap(gi), f_ = sig_ap(gf), g_ = tanh_ap(gg), o_ = sig_ap(go);
        creg = f_ * creg + i_ * g_;
        float h_ = o_ * tanh_ap(creg);
        out[((size_t)(bb + ebb) * TT + t) * DD + koff + ej] = h_;   // coalesced per warp

        float hrd = __uint_as_float(tf32r(h_));       // tf32-round the recurrence operand
        hsm[wb + (koff + ej) * 8 + ebb] = hrd;        // local copy
        asm volatile("st.shared::cluster.f32 [%0], %1;"
                     :: "r"(remBase + (unsigned)(wb * 4) + myoff), "f"(hrd) : "memory");
        CLUSTER_SYNC();                               // h exchange complete; orders DSMEM
    }
}

// ---------------- launch ----------------
extern "C" void kernel_launch(void* const* d_in, const int* in_sizes, int n_in,
                              void* d_out, int out_size) {
    const float* x     = (const float*)d_in[0];
    const float* Wih_e = (const float*)d_in[1];
    const float* Whh_e = (const float*)d_in[2];
    const float* b_e   = (const float*)d_in[3];
    const float* Wih_d = (const float*)d_in[4];
    const float* Whh_d = (const float*)d_in[5];
    const float* b_d   = (const float*)d_in[6];
    float* out = (float*)d_out;

    cudaFuncSetAttribute(enc_kernel, cudaFuncAttributeMaxDynamicSharedMemorySize, ENC_SMEM_BYTES);
    cudaFuncSetAttribute(dec_kernel, cudaFuncAttributeMaxDynamicSharedMemorySize, DEC_SMEM_BYTES);

    prep_kernel<<<576, 256>>>(Wih_e, Whh_e, Whh_d, Wih_d);
    enc_kernel<<<BATCH / 4, 256, ENC_SMEM_BYTES>>>(x, b_e);
    dec_kernel<<<BATCH / 8 * 2, 512, DEC_SMEM_BYTES>>>(b_d, out);   // 128 CTAs = 64 clusters of 2
}

// round 13
// speedup vs baseline: 2.7374x; 1.4248x over previous
#include <cuda_runtime.h>
#include <math.h>

// Problem dims
#define BATCH 512
#define TT    512
#define DD    128
#define HH    64

#define GE 256      // encoder gates 4H
#define KE 192      // encoder K = D + H
#define GD 512      // decoder gates 4D
#define KD 128      // decoder K = D

typedef unsigned long long u64t;

// ---------------- device scratch ----------------
__device__ __align__(16) float g_WeFrag[2 * 8 * 24 * 128];  // 49152: encoder Whh+Wih tf32 mma fragments
__device__ __align__(16) float g_WdFrag[2 * 16 * 16 * 128]; // 65536: decoder Whh tf32 mma fragments
__device__ __align__(16) float g_Wihd2[2 * HH * 256];       // 32768: decoder input proj [role][k][lrow]
__device__ __align__(16) float g_henc  [BATCH * HH];

// ---------------- helpers ----------------
__device__ __forceinline__ float tanh_ap(float x) {
    asm("tanh.approx.f32 %0, %0;" : "+f"(x)); return x;
}
__device__ __forceinline__ float sig_ap(float x) {
    return fmaf(tanh_ap(0.5f * x), 0.5f, 0.5f);
}
__device__ __forceinline__ unsigned tf32r(float f) {
    unsigned u; asm("cvt.rna.tf32.f32 %0, %1;" : "=r"(u) : "f"(f)); return u;
}
__device__ __forceinline__ float tf32f(float f) { return __uint_as_float(tf32r(f)); }
__device__ __forceinline__ void mma_tf32(float d[4],
                                         unsigned a0, unsigned a1, unsigned a2, unsigned a3,
                                         unsigned b0, unsigned b1) {
    asm volatile(
        "mma.sync.aligned.m16n8k8.row.col.f32.tf32.tf32.f32 "
        "{%0,%1,%2,%3}, {%4,%5,%6,%7}, {%8,%9}, {%0,%1,%2,%3};"
        : "+f"(d[0]), "+f"(d[1]), "+f"(d[2]), "+f"(d[3])
        : "r"(a0), "r"(a1), "r"(a2), "r"(a3), "r"(b0), "r"(b1));
}
#define CLUSTER_SYNC() do { \
    asm volatile("barrier.cluster.arrive.aligned;" ::: "memory"); \
    asm volatile("barrier.cluster.wait.aligned;" ::: "memory"); \
} while (0)

// ---------------- prep: build tf32 mma fragments (one-time, tiny) ----------------
__global__ void prep_kernel(const float* __restrict__ Wih_e,
                            const float* __restrict__ Whh_e,
                            const float* __restrict__ Whh_d,
                            const float* __restrict__ Wih_d) {
    int idx = blockIdx.x * 256 + threadIdx.x;            // 0 .. 147455
    if (idx < 49152) {                                   // encoder fragments
        int wblk = idx / 3072;                           // role*8 + w
        int rem  = idx - wblk * 3072;
        int kt = rem >> 7;                               // 0..23
        int r2 = rem & 127;
        int l = r2 >> 2, c = r2 & 3;
        int gr = l >> 2, gc = l & 3;
        int row = (wblk >> 3) * 128 + (wblk & 7) * 16 + gr + (c & 1) * 8;   // 0..255
        int k   = kt * 8 + gc + ((c >> 1) & 1) * 4;                          // 0..191
        float v = (k < DD) ? Wih_e[row * DD + k] : Whh_e[row * HH + (k - DD)];
        g_WeFrag[idx] = __uint_as_float(tf32r(v));
        return;
    }
    int f = idx - 49152;
    if (f < 65536) {                                     // decoder fragments (R11, validated)
        int rw = f >> 11;
        int role = rw >> 4, w = rw & 15;
        int rem = f & 2047;
        int i4 = rem >> 7;
        int r2 = rem & 127;
        int l = r2 >> 2, c = r2 & 3;
        int gr = l >> 2, gc = l & 3;
        int lrow = w * 16 + gr + (c & 1) * 8;
        int k = i4 * 8 + gc + ((c >> 1) & 1) * 4;
        int gate = lrow >> 6, j = lrow & 63;
        int grow = gate * 128 + role * 64 + j;
        g_WdFrag[f] = __uint_as_float(tf32r(Whh_d[grow * 128 + k]));
        return;
    }
    int f2 = f - 65536;
    if (f2 < 32768) {                                    // decoder input proj [role][k][lrow]
        int rolek = f2 >> 8, lr = f2 & 255;
        int role = rolek >> 6, k = rolek & 63;
        int gate = lr >> 6, j = lr & 63;
        int grow = gate * 128 + role * 64 + j;
        g_Wihd2[f2] = Wih_d[grow * 64 + k];
    }
}

// ---------------- encoder: 2-CTA cluster, register-resident tf32 mma ----------------
// 64 clusters x 2 CTAs x 8 batches; 256 threads/CTA; CTA role r owns gate rows [r*128, r*128+128).
// SMEM floats: xs[8][132] 1056 | hs[2][8][72] 1152 | gsm[2][256][9] 4608
#define EXS 0
#define EHS 1056
#define EGS 2208
#define ENC_SMEM_F (EGS + 4608)
#define ENC_SMEM_BYTES (ENC_SMEM_F * 4)

__global__ __launch_bounds__(256, 1) __cluster_dims__(2, 1, 1)
void enc_kernel(const float* __restrict__ x, const float* __restrict__ b_e) {
    extern __shared__ float sm[];
    float* xs  = sm + EXS;     // [b][132]   x_t staging (k contiguous)
    float* hs  = sm + EHS;     // [2][b][72] double-buffered hidden
    float* gsm = sm + EGS;     // [2][256 row][9 b] double-buffered gates

    const int tid = threadIdx.x;
    const int w = tid >> 5, l = tid & 31;
    const int gr = l >> 2, gc = l & 3;
    unsigned rank;
    asm("mov.u32 %0, %%cluster_ctarank;" : "=r"(rank));
    const int bb = (blockIdx.x >> 1) * 8;

    // A fragments: 24 k-tiles x float4, coalesced
    float4 af[24];
    {
        const float4* Asrc = (const float4*)g_WeFrag + ((int)rank * 8 + w) * 768;
        #pragma unroll
        for (int kt = 0; kt < 24; ++kt) af[kt] = Asrc[kt * 32 + l];
    }
    const int row0 = (int)rank * 128 + w * 16 + gr;      // global gate rows this thread owns
    const float bsr0 = b_e[row0], bsr1 = b_e[row0 + 8];

    // zero hidden buffers
    for (int i = tid; i < 1152; i += 256) hs[i] = 0.0f;

    // stage x_0 (tf32-rounded)
    const int xb = tid >> 5, xk = (tid & 31) * 4;
    {
        float4 v = *(const float4*)&x[(size_t)(bb + xb) * TT * DD + xk];
        float* d = &xs[xb * 132 + xk];
        d[0] = tf32f(v.x); d[1] = tf32f(v.y); d[2] = tf32f(v.z); d[3] = tf32f(v.w);
    }
    __syncthreads();
    CLUSTER_SYNC();

    // remote gsm base (peer CTA)
    unsigned gU = (unsigned)__cvta_generic_to_shared(gsm);
    unsigned remG;
    asm("mapa.shared::cluster.u32 %0, %1, %2;" : "=r"(remG) : "r"(gU), "r"(rank ^ 1u));

    const int ej = tid & 63, eb = tid >> 6;              // elementwise: (j, eb) and (j, eb+4)
    float c0 = 0.0f, c1 = 0.0f, h0 = 0.0f, h1 = 0.0f;

    for (int t = 0; t < TT; ++t) {
        // prefetch x_{t+1} early (consumed after cluster sync)
        float4 xn = make_float4(0.f, 0.f, 0.f, 0.f);
        if (t + 1 < TT)
            xn = *(const float4*)&x[(size_t)(bb + xb) * TT * DD + (size_t)(t + 1) * DD + xk];

        const int rb = (t & 1) ^ 1;                      // h read buffer
        const int wbuf = t & 1;                          // gate buffer for this step

        float dd[4] = {bsr0, bsr0, bsr1, bsr1};
        float ee[4] = {0.f, 0.f, 0.f, 0.f};
        // x part: kt 0..15
        #pragma unroll
        for (int kt = 0; kt < 16; ++kt) {
            float b0 = xs[gr * 132 + kt * 8 + gc];
            float b1 = xs[gr * 132 + kt * 8 + gc + 4];
            mma_tf32((kt & 1) ? ee : dd,
                     __float_as_uint(af[kt].x), __float_as_uint(af[kt].y),
                     __float_as_uint(af[kt].z), __float_as_uint(af[kt].w),
                     __float_as_uint(b0), __float_as_uint(b1));
        }
        // h part: kt 16..23
        #pragma unroll
        for (int kt = 16; kt < 24; ++kt) {
            int kk = (kt - 16) * 8;
            float b0 = hs[(rb * 8 + gr) * 72 + kk + gc];
            float b1 = hs[(rb * 8 + gr) * 72 + kk + gc + 4];
            mma_tf32((kt & 1) ? ee : dd,
                     __float_as_uint(af[kt].x), __float_as_uint(af[kt].y),
                     __float_as_uint(af[kt].z), __float_as_uint(af[kt].w),
                     __float_as_uint(b0), __float_as_uint(b1));
        }
        float g0 = dd[0] + ee[0], g1 = dd[1] + ee[1];
        float g2 = dd[2] + ee[2], g3 = dd[3] + ee[3];

        // store my gate block locally AND to peer (same offsets)
        {
            unsigned o0 = (unsigned)(((wbuf * 256 + row0) * 9 + 2 * gc) * 4);
            unsigned o1 = (unsigned)(((wbuf * 256 + row0 + 8) * 9 + 2 * gc) * 4);
            gsm[(wbuf * 256 + row0) * 9 + 2 * gc]         = g0;
            gsm[(wbuf * 256 + row0) * 9 + 2 * gc + 1]     = g1;
            gsm[(wbuf * 256 + row0 + 8) * 9 + 2 * gc]     = g2;
            gsm[(wbuf * 256 + row0 + 8) * 9 + 2 * gc + 1] = g3;
            asm volatile("st.shared::cluster.f32 [%0], %1;" :: "r"(remG + o0),     "f"(g0) : "memory");
            asm volatile("st.shared::cluster.f32 [%0], %1;" :: "r"(remG + o0 + 4), "f"(g1) : "memory");
            asm volatile("st.shared::cluster.f32 [%0], %1;" :: "r"(remG + o1),     "f"(g2) : "memory");
            asm volatile("st.shared::cluster.f32 [%0], %1;" :: "r"(remG + o1 + 4), "f"(g3) : "memory");
        }
        CLUSTER_SYNC();                                  // peer's gate half has arrived

        // elementwise (both CTAs compute full h) — 2 cells per thread
        {
            const float* gb = gsm + wbuf * 256 * 9;
            float gi = gb[(ej)       * 9 + eb];
            float gf = gb[(64 + ej)  * 9 + eb];
            float gg = gb[(128 + ej) * 9 + eb];
            float go = gb[(192 + ej) * 9 + eb];
            float i_ = sig_ap(gi), f_ = sig_ap(gf), gv = tanh_ap(gg), o_ = sig_ap(go);
            c0 = f_ * c0 + i_ * gv;
            h0 = o_ * tanh_ap(c0);
            hs[(wbuf * 8 + eb) * 72 + ej] = tf32f(h0);

            gi = gb[(ej)       * 9 + eb + 4];
            gf = gb[(64 + ej)  * 9 + eb + 4];
            gg = gb[(128 + ej) * 9 + eb + 4];
            go = gb[(192 + ej) * 9 + eb + 4];
            i_ = sig_ap(gi); f_ = sig_ap(gf); gv = tanh_ap(gg); o_ = sig_ap(go);
            c1 = f_ * c1 + i_ * gv;
            h1 = o_ * tanh_ap(c1);
            hs[(wbuf * 8 + eb + 4) * 72 + ej] = tf32f(h1);
        }
        // commit x_{t+1}
        {
            float* d = &xs[xb * 132 + xk];
            d[0] = tf32f(xn.x); d[1] = tf32f(xn.y); d[2] = tf32f(xn.z); d[3] = tf32f(xn.w);
        }
        __syncthreads();
    }
    g_henc[(bb + eb) * HH + ej]     = h0;
    g_henc[(bb + eb + 4) * HH + ej] = h1;
}

// ---------------- decoder: R11 cluster mma kernel + dual accumulators ----------------
#define DEC_SMEM_F (2048 + 2048 + 2560)
#define DEC_SMEM_BYTES (DEC_SMEM_F * 4)

__global__ __launch_bounds__(512, 1) __cluster_dims__(2, 1, 1)
void dec_kernel(const float* __restrict__ b_d, float* __restrict__ out) {
    extern __shared__ float sm[];
    float* hsm = sm;              // [2][128 k][8 b]
    float* xp  = sm + 2048;       // [256 lrow][8 b]
    float* gsm = sm + 4096;       // [256 lrow][10]
    float* hesm = gsm;            // reuse for h_enc staging

    const int tid = threadIdx.x;
    const int w = tid >> 5, l = tid & 31;
    unsigned rank;
    asm("mov.u32 %0, %%cluster_ctarank;" : "=r"(rank));
    const int bb   = (blockIdx.x >> 1) * 8;
    const int koff = (int)rank * 64;

    float4 af[16];
    {
        const float4* Asrc = (const float4*)g_WdFrag + ((int)rank * 16 + w) * 512;
        #pragma unroll
        for (int i4 = 0; i4 < 16; ++i4) af[i4] = Asrc[i4 * 32 + l];
    }

    hsm[tid] = 0.0f; hsm[512 + tid] = 0.0f;
    hsm[1024 + tid] = 0.0f; hsm[1536 + tid] = 0.0f;
    hesm[tid] = g_henc[bb * 64 + tid];
    __syncthreads();

    {
        int lr = tid >> 1, b4 = (tid & 1) * 4;
        int gate = lr >> 6, j = lr & 63;
        int grow = gate * 128 + koff + j;
        float a0 = b_d[grow], a1 = a0, a2 = a0, a3 = a0;
        #pragma unroll 4
        for (int k = 0; k < HH; ++k) {
            float ww = g_Wihd2[((int)rank * 64 + k) * 256 + lr];
            a0 = fmaf(ww, hesm[(b4 + 0) * 64 + k], a0);
            a1 = fmaf(ww, hesm[(b4 + 1) * 64 + k], a1);
            a2 = fmaf(ww, hesm[(b4 + 2) * 64 + k], a2);
            a3 = fmaf(ww, hesm[(b4 + 3) * 64 + k], a3);
        }
        *(float4*)&xp[lr * 8 + b4] = make_float4(a0, a1, a2, a3);
    }
    __syncthreads();
    CLUSTER_SYNC();

    const int gr = l >> 2, gc = l & 3;
    const int wbase = w * 16;
    const int ej = tid & 63, ebb = tid >> 6;
    float creg = 0.0f;

    unsigned hU = (unsigned)__cvta_generic_to_shared(hsm);
    unsigned remBase;
    asm("mapa.shared::cluster.u32 %0, %1, %2;" : "=r"(remBase) : "r"(hU), "r"(rank ^ 1u));
    const unsigned myoff = (unsigned)(((koff + ej) * 8 + ebb) * 4);

    for (int t = 0; t < TT; ++t) {
        const float* hr = hsm + (((t & 1) ^ 1) << 10);
        const int wb = (t & 1) << 10;

        float2 x01 = *(const float2*)&xp[(wbase + gr) * 8 + 2 * gc];
        float2 x23 = *(const float2*)&xp[(wbase + gr + 8) * 8 + 2 * gc];
        float dd[4] = {x01.x, x01.y, x23.x, x23.y};
        float ee[4] = {0.f, 0.f, 0.f, 0.f};

        #pragma unroll
        for (int kt = 0; kt < 16; ++kt) {
            float b0 = hr[(kt * 8 + gc) * 8 + gr];
            float b1 = hr[(kt * 8 + gc + 4) * 8 + gr];
            mma_tf32((kt & 1) ? ee : dd,
                     __float_as_uint(af[kt].x), __float_as_uint(af[kt].y),
                     __float_as_uint(af[kt].z), __float_as_uint(af[kt].w),
                     __float_as_uint(b0), __float_as_uint(b1));
        }
        *(float2*)&gsm[(wbase + gr) * 10 + 2 * gc]     = make_float2(dd[0] + ee[0], dd[1] + ee[1]);
        *(float2*)&gsm[(wbase + gr + 8) * 10 + 2 * gc] = make_float2(dd[2] + ee[2], dd[3] + ee[3]);
        __syncthreads();

        float gi = gsm[(ej)       * 10 + ebb];
        float gf = gsm[(64 + ej)  * 10 + ebb];
        float gg = gsm[(128 + ej) * 10 + ebb];
        float go = gsm[(192 + ej) * 10 + ebb];
        float i_ = sig_ap(gi), f_ = sig_ap(gf), g_ = tanh_ap(gg), o_ = sig_ap(go);
        creg = f_ * creg + i_ * g_;
        float h_ = o_ * tanh_ap(creg);
        out[((size_t)(bb + ebb) * TT + t) * DD + koff + ej] = h_;

        float hrd = __uint_as_float(tf32r(h_));
        hsm[wb + (koff + ej) * 8 + ebb] = hrd;
        asm volatile("st.shared::cluster.f32 [%0], %1;"
                     :: "r"(remBase + (unsigned)(wb * 4) + myoff), "f"(hrd) : "memory");
        CLUSTER_SYNC();
    }
}

// ---------------- launch ----------------
extern "C" void kernel_launch(void* const* d_in, const int* in_sizes, int n_in,
                              void* d_out, int out_size) {
    const float* x     = (const float*)d_in[0];
    const float* Wih_e = (const float*)d_in[1];
    const float* Whh_e = (const float*)d_in[2];
    const float* b_e   = (const float*)d_in[3];
    const float* Wih_d = (const float*)d_in[4];
    const float* Whh_d = (const float*)d_in[5];
    const float* b_d   = (const float*)d_in[6];
    float* out = (float*)d_out;

    cudaFuncSetAttribute(enc_kernel, cudaFuncAttributeMaxDynamicSharedMemorySize, ENC_SMEM_BYTES);
    cudaFuncSetAttribute(dec_kernel, cudaFuncAttributeMaxDynamicSharedMemorySize, DEC_SMEM_BYTES);

    prep_kernel<<<576, 256>>>(Wih_e, Whh_e, Whh_d, Wih_d);
    enc_kernel<<<BATCH / 8 * 2, 256, ENC_SMEM_BYTES>>>(x, b_e);   // 128 CTAs = 64 clusters
    dec_kernel<<<BATCH / 8 * 2, 512, DEC_SMEM_BYTES>>>(b_d, out); // 128 CTAs = 64 clusters
}